// round 1
// baseline (speedup 1.0000x reference)
#include <cuda_runtime.h>

#define BLOCK 128
#define NROWS 262144

// ---------------- shared memory layout (floats) ----------------
// Big float4-read blocks first (offsets multiple of 4).
constexpr int OFF_W1F  = 0;                  // folded up_m_w1: 64 rows x 44 (36 sym pairs + 8 hm)
constexpr int OFF_W2   = OFF_W1F + 64 * 44;  // up_m_w2 64x64
constexpr int OFF_W3   = OFF_W2  + 64 * 64;  // up_m_w3 72x64
constexpr int OFF_F1F  = OFF_W3  + 72 * 64;  // folded fr_w1: 64x44
constexpr int OFF_F2   = OFF_F1F + 64 * 44;  // fr_w2 64x64
constexpr int OFF_F3   = OFF_F2  + 64 * 64;  // fr_w3 8x64
constexpr int OFF_B1   = OFF_F3  + 8 * 64;   // up_m_b1 64
constexpr int OFF_B2   = OFF_B1  + 64;       // up_m_b2 64
constexpr int OFF_B3   = OFF_B2  + 64;       // up_m_b3 72
constexpr int OFF_FB1  = OFF_B3  + 72;       // fr_b1 64
constexpr int OFF_FB2  = OFF_FB1 + 64;       // fr_b2 64
constexpr int OFF_FB3  = OFF_FB2 + 64;       // fr_b3 8
constexpr int OFF_UZ1  = OFF_FB3 + 8;        // up_Z1_w 8x4
constexpr int OFF_UH1W = OFF_UZ1 + 32;       // up_h1_w 8x13
constexpr int OFF_UH1B = OFF_UH1W + 104;     // up_h1_b 8
constexpr int OFF_G1W  = OFF_UH1B + 8;       // up_g1_w1 first 8 cols: 8x8
constexpr int OFF_G1B  = OFF_G1W + 64;       // 8
constexpr int OFF_G2W  = OFF_G1B + 8;        // up_g1_w2 8
constexpr int OFF_G2B  = OFF_G2W + 8;        // 1 (padded)
constexpr int OFF_UZ2S = OFF_G2B + 4;        // up_Z2_w cols 0..7: 8x8
constexpr int OFF_UZ2Z = OFF_UZ2S + 64;      // up_Z2_w col 24: 8
constexpr int OFF_DG1W = OFF_UZ2Z + 8;       // dn_g1_w1 first 8 cols: 8x8
constexpr int OFF_DG1B = OFF_DG1W + 64;      // 8
constexpr int OFF_DG2W = OFF_DG1B + 8;       // 8
constexpr int OFF_DG2B = OFF_DG2W + 8;       // 1 (padded)
constexpr int OFF_DZ2S = OFF_DG2B + 4;       // dn_Z2_w cols 0..7: 8x8
constexpr int OFF_DZ2Z = OFF_DZ2S + 64;      // dn_Z2_w col 16: 8
constexpr int SMEM_FLOATS = OFF_DZ2Z + 8;

__device__ __forceinline__ float dot44(const float* __restrict__ smrow, const float* xv) {
    const float4* w = reinterpret_cast<const float4*>(smrow);
    float a = 0.f;
#pragma unroll
    for (int q = 0; q < 11; q++) {
        float4 wv = w[q];
        a += wv.x * xv[4 * q] + wv.y * xv[4 * q + 1] + wv.z * xv[4 * q + 2] + wv.w * xv[4 * q + 3];
    }
    return a;
}

__device__ __forceinline__ float dot64(const float* __restrict__ smrow, const float* xv) {
    const float4* w = reinterpret_cast<const float4*>(smrow);
    float a = 0.f;
#pragma unroll
    for (int q = 0; q < 16; q++) {
        float4 wv = w[q];
        a += wv.x * xv[4 * q] + wv.y * xv[4 * q + 1] + wv.z * xv[4 * q + 2] + wv.w * xv[4 * q + 3];
    }
    return a;
}

__global__ void __launch_bounds__(BLOCK) frame_gnn_kernel(
    const float* __restrict__ state,
    const float* __restrict__ up_Z1_w, const float* __restrict__ up_h1_w, const float* __restrict__ up_h1_b,
    const float* __restrict__ up_g1_w1, const float* __restrict__ up_g1_b1,
    const float* __restrict__ up_g1_w2, const float* __restrict__ up_g1_b2,
    const float* __restrict__ up_Z2_w,
    const float* __restrict__ up_m_w1, const float* __restrict__ up_m_b1,
    const float* __restrict__ up_m_w2, const float* __restrict__ up_m_b2,
    const float* __restrict__ up_m_w3, const float* __restrict__ up_m_b3,
    const float* __restrict__ dn_g1_w1, const float* __restrict__ dn_g1_b1,
    const float* __restrict__ dn_g1_w2, const float* __restrict__ dn_g1_b2,
    const float* __restrict__ dn_Z2_w,
    const float* __restrict__ fr_w1, const float* __restrict__ fr_b1,
    const float* __restrict__ fr_w2, const float* __restrict__ fr_b2,
    const float* __restrict__ fr_w3, const float* __restrict__ fr_b3,
    float* __restrict__ out)
{
    extern __shared__ float sm[];
    const int tid = threadIdx.x;

    // ---------------- stage + fold weights into shared ----------------
    if (tid < 64) {
        const int k = tid;
        int p = 0;
        for (int a = 0; a < 8; a++) {
            for (int b = a; b < 8; b++) {
                float w = up_m_w1[k * 88 + a * 8 + b];
                float f = fr_w1[k * 80 + a * 8 + b];
                if (a != b) {
                    w += up_m_w1[k * 88 + b * 8 + a];
                    f += fr_w1[k * 80 + b * 8 + a];
                }
                sm[OFF_W1F + k * 44 + p] = w;
                sm[OFF_F1F + k * 44 + p] = f;
                p++;
            }
        }
        for (int j = 0; j < 8; j++) {
            sm[OFF_W1F + k * 44 + 36 + j] = up_m_w1[k * 88 + 64 + j];
            sm[OFF_F1F + k * 44 + 36 + j] = fr_w1[k * 80 + 64 + j];
        }
    }
    for (int i = tid; i < 64 * 64; i += BLOCK) { sm[OFF_W2 + i] = up_m_w2[i]; sm[OFF_F2 + i] = fr_w2[i]; }
    for (int i = tid; i < 72 * 64; i += BLOCK) sm[OFF_W3 + i] = up_m_w3[i];
    for (int i = tid; i < 8 * 64; i += BLOCK) sm[OFF_F3 + i] = fr_w3[i];
    for (int i = tid; i < 64; i += BLOCK) {
        sm[OFF_B1 + i] = up_m_b1[i]; sm[OFF_B2 + i] = up_m_b2[i];
        sm[OFF_FB1 + i] = fr_b1[i];  sm[OFF_FB2 + i] = fr_b2[i];
    }
    for (int i = tid; i < 72; i += BLOCK) sm[OFF_B3 + i] = up_m_b3[i];
    for (int i = tid; i < 104; i += BLOCK) sm[OFF_UH1W + i] = up_h1_w[i];
    for (int i = tid; i < 32; i += BLOCK) sm[OFF_UZ1 + i] = up_Z1_w[i];
    for (int i = tid; i < 64; i += BLOCK) {
        const int k = i >> 3, j = i & 7;
        sm[OFF_G1W + i]  = up_g1_w1[k * 24 + j];
        sm[OFF_DG1W + i] = dn_g1_w1[k * 16 + j];
        sm[OFF_UZ2S + i] = up_Z2_w[k * 25 + j];
        sm[OFF_DZ2S + i] = dn_Z2_w[k * 17 + j];
    }
    if (tid < 8) {
        sm[OFF_FB3 + tid]  = fr_b3[tid];
        sm[OFF_UH1B + tid] = up_h1_b[tid];
        sm[OFF_G1B + tid]  = up_g1_b1[tid];
        sm[OFF_G2W + tid]  = up_g1_w2[tid];
        sm[OFF_UZ2Z + tid] = up_Z2_w[tid * 25 + 24];
        sm[OFF_DG1B + tid] = dn_g1_b1[tid];
        sm[OFF_DG2W + tid] = dn_g1_w2[tid];
        sm[OFF_DZ2Z + tid] = dn_Z2_w[tid * 17 + 16];
    }
    if (tid == 0) { sm[OFF_G2B] = up_g1_b2[0]; sm[OFF_DG2B] = dn_g1_b2[0]; }
    __syncthreads();

    // ---------------- per-row compute ----------------
    const int row = blockIdx.x * BLOCK + tid;
    const float* s = state + (size_t)row * 25;
    float* o = out + (size_t)row * 25;

    float h0[13];
#pragma unroll
    for (int i = 0; i < 4; i++) { float v = s[i]; h0[i] = v; o[i] = v; }
#pragma unroll
    for (int i = 0; i < 9; i++) { float v = s[16 + i]; h0[4 + i] = v; o[16 + i] = v; }
    float Z0x[4], Z0y[4], Z0z[4];
#pragma unroll
    for (int j = 0; j < 4; j++) { Z0x[j] = s[4 + 3 * j]; Z0y[j] = s[5 + 3 * j]; Z0z[j] = s[6 + 3 * j]; }

    // hm8 = relu(up_h1 @ h0 + b)
    float hm8[8];
#pragma unroll
    for (int k = 0; k < 8; k++) {
        float a = sm[OFF_UH1B + k];
#pragma unroll
        for (int i = 0; i < 13; i++) a += h0[i] * sm[OFF_UH1W + k * 13 + i];
        hm8[k] = fmaxf(a, 0.f);
    }
    // gs (scalar gate)
    float gs = sm[OFF_G2B];
#pragma unroll
    for (int k = 0; k < 8; k++) {
        float a = sm[OFF_G1B + k];
#pragma unroll
        for (int i = 0; i < 8; i++) a += hm8[i] * sm[OFF_G1W + k * 8 + i];
        gs += fmaxf(a, 0.f) * sm[OFF_G2W + k];
    }
    // Zu = Z0 @ up_Z1_w^T ; Zm = [Zu, 0s, (0,0,gs)] @ up_Z2_w^T
    float Zm0[8], Zm1[8], Zm2a[8];
    {
        float Zu0[8], Zu1[8], Zu2[8];
#pragma unroll
        for (int k = 0; k < 8; k++) {
            float a0 = 0.f, a1 = 0.f, a2 = 0.f;
#pragma unroll
            for (int j = 0; j < 4; j++) {
                float w = sm[OFF_UZ1 + k * 4 + j];
                a0 += Z0x[j] * w; a1 += Z0y[j] * w; a2 += Z0z[j] * w;
            }
            Zu0[k] = a0; Zu1[k] = a1; Zu2[k] = a2;
        }
#pragma unroll
        for (int k = 0; k < 8; k++) {
            float a0 = 0.f, a1 = 0.f, a2 = 0.f;
#pragma unroll
            for (int m = 0; m < 8; m++) {
                float w = sm[OFF_UZ2S + k * 8 + m];
                a0 += Zu0[m] * w; a1 += Zu1[m] * w; a2 += Zu2[m] * w;
            }
            a2 += gs * sm[OFF_UZ2Z + k];
            Zm0[k] = a0; Zm1[k] = a1; Zm2a[k] = a2;
        }
    }
    // Mf (symmetric Gram -> 36 unique) + Frobenius norm
    float xv[44];
    float nrm = 0.f;
    {
        int p = 0;
#pragma unroll
        for (int a = 0; a < 8; a++)
#pragma unroll
            for (int b = a; b < 8; b++) {
                float v = Zm0[a] * Zm0[b] + Zm1[a] * Zm1[b] + Zm2a[a] * Zm2a[b];
                xv[p] = v;
                nrm += (a == b) ? v * v : 2.f * v * v;
                p++;
            }
    }
#pragma unroll
    for (int j = 0; j < 8; j++) xv[36 + j] = hm8[j];
    const float invFn = 1.f / (sqrtf(nrm) + 1.f);

    // up_m MLP: layer1 (folded 44-in), layer2 (64), layer3 fused with up_Z accumulate
    float t1[64];
#pragma unroll
    for (int k = 0; k < 64; k++)
        t1[k] = fmaxf(sm[OFF_B1 + k] + dot44(&sm[OFF_W1F + k * 44], xv), 0.f);
    float t2[64];
#pragma unroll
    for (int k = 0; k < 64; k++)
        t2[k] = fmaxf(sm[OFF_B2 + k] + dot64(&sm[OFF_W2 + k * 64], t1), 0.f);

    float uZ0[8], uZ1[8], uZ2[8];
#pragma unroll
    for (int k = 0; k < 8; k++) { uZ0[k] = 0.f; uZ1[k] = 0.f; uZ2[k] = 0.f; }
#pragma unroll
    for (int j = 0; j < 8; j++) {
#pragma unroll
        for (int k = 0; k < 8; k++) {
            const int idx = j * 8 + k;
            float m = (sm[OFF_B3 + idx] + dot64(&sm[OFF_W3 + idx * 64], t2)) * invFn;
            uZ0[k] += Zm0[j] * m; uZ1[k] += Zm1[j] * m; uZ2[k] += Zm2a[j] * m;
        }
    }
    float hm2[8];
#pragma unroll
    for (int j = 0; j < 8; j++) {
        const int idx = 64 + j;
        float m = (sm[OFF_B3 + idx] + dot64(&sm[OFF_W3 + idx * 64], t2)) * invFn;
        hm2[j] = fmaxf(m, 0.f);
    }
    // gs2
    float gs2 = sm[OFF_DG2B];
#pragma unroll
    for (int k = 0; k < 8; k++) {
        float a = sm[OFF_DG1B + k];
#pragma unroll
        for (int i = 0; i < 8; i++) a += hm2[i] * sm[OFF_DG1W + k * 8 + i];
        gs2 += fmaxf(a, 0.f) * sm[OFF_DG2W + k];
    }
    // Zm2 = [up_Z, 0s, (0,0,gs2)] @ dn_Z2_w^T
    float Y0[8], Y1[8], Y2[8];
#pragma unroll
    for (int k = 0; k < 8; k++) {
        float a0 = 0.f, a1 = 0.f, a2 = 0.f;
#pragma unroll
        for (int j = 0; j < 8; j++) {
            float w = sm[OFF_DZ2S + k * 8 + j];
            a0 += uZ0[j] * w; a1 += uZ1[j] * w; a2 += uZ2[j] * w;
        }
        a2 += gs2 * sm[OFF_DZ2Z + k];
        Y0[k] = a0; Y1[k] = a1; Y2[k] = a2;
    }
    // M2f pairs + norm
    float nrm2 = 0.f;
    {
        int p = 0;
#pragma unroll
        for (int a = 0; a < 8; a++)
#pragma unroll
            for (int b = a; b < 8; b++) {
                float v = Y0[a] * Y0[b] + Y1[a] * Y1[b] + Y2[a] * Y2[b];
                xv[p] = v;
                nrm2 += (a == b) ? v * v : 2.f * v * v;
                p++;
            }
    }
#pragma unroll
    for (int j = 0; j < 8; j++) xv[36 + j] = hm2[j];
    const float invFn2 = 1.f / (sqrtf(nrm2) + 1.f);

    // fr MLP
    float f1[64];
#pragma unroll
    for (int k = 0; k < 64; k++)
        f1[k] = fmaxf(sm[OFF_FB1 + k] + dot44(&sm[OFF_F1F + k * 44], xv), 0.f);
    float f2[64];
#pragma unroll
    for (int k = 0; k < 64; k++)
        f2[k] = fmaxf(sm[OFF_FB2 + k] + dot64(&sm[OFF_F2 + k * 64], f1), 0.f);
    float frv[8];
#pragma unroll
    for (int k = 0; k < 8; k++)
        frv[k] = (sm[OFF_FB3 + k] + dot64(&sm[OFF_F3 + k * 64], f2)) * invFn2;

    // frame (only x,y needed — z is masked by _basis)
    float fx = 0.f, fy = 0.f;
#pragma unroll
    for (int k = 0; k < 8; k++) { fx += Y0[k] * frv[k]; fy += Y1[k] * frv[k]; }
    const float n = sqrtf(fx * fx + fy * fy) + 1e-6f;
    const float u1x = fx / n, u1y = fy / n;

    // Z_rot = R^T Z0 ; write interleaved back into out[4:16]
#pragma unroll
    for (int j = 0; j < 4; j++) {
        o[4 + 3 * j]     = u1x * Z0x[j] + u1y * Z0y[j];
        o[4 + 3 * j + 1] = -u1y * Z0x[j] + u1x * Z0y[j];
        o[4 + 3 * j + 2] = Z0z[j];
    }
}

extern "C" void kernel_launch(void* const* d_in, const int* in_sizes, int n_in,
                              void* d_out, int out_size) {
    (void)in_sizes; (void)n_in; (void)out_size;
    const size_t smem_bytes = SMEM_FLOATS * sizeof(float);
    cudaFuncSetAttribute(frame_gnn_kernel, cudaFuncAttributeMaxDynamicSharedMemorySize,
                         (int)smem_bytes);
    frame_gnn_kernel<<<NROWS / BLOCK, BLOCK, smem_bytes>>>(
        (const float*)d_in[0],
        (const float*)d_in[1], (const float*)d_in[2], (const float*)d_in[3],
        (const float*)d_in[4], (const float*)d_in[5], (const float*)d_in[6], (const float*)d_in[7],
        (const float*)d_in[8],
        (const float*)d_in[9], (const float*)d_in[10], (const float*)d_in[11], (const float*)d_in[12],
        (const float*)d_in[13], (const float*)d_in[14],
        (const float*)d_in[15], (const float*)d_in[16], (const float*)d_in[17], (const float*)d_in[18],
        (const float*)d_in[19],
        (const float*)d_in[20], (const float*)d_in[21], (const float*)d_in[22], (const float*)d_in[23],
        (const float*)d_in[24], (const float*)d_in[25],
        (float*)d_out);
}

// round 2
// speedup vs baseline: 1.6812x; 1.6812x over previous
#include <cuda_runtime.h>

#define BLOCK 256
#define NROWS 262144

using ull = unsigned long long;

// ---------------- shared memory layout (floats) ----------------
// Packed pair-interleaved weights: element (pair p, input j) at OFF + (p*K + j)*2,
// storing (W[2p][j], W[2p+1][j]) in consecutive floats (lo, hi of a b64).
constexpr int OFF_L1  = 0;                    // up_m_w1 folded: 32 pairs x 44
constexpr int OFF_L2  = OFF_L1 + 32 * 44 * 2; // up_m_w2: 32 pairs x 64
constexpr int OFF_L3  = OFF_L2 + 32 * 64 * 2; // up_m_w3: 36 pairs x 64
constexpr int OFF_F1  = OFF_L3 + 36 * 64 * 2; // fr_w1 folded: 32 x 44
constexpr int OFF_F2  = OFF_F1 + 32 * 44 * 2; // fr_w2: 32 x 64
constexpr int OFF_F3  = OFF_F2 + 32 * 64 * 2; // fr_w3: 4 x 64
constexpr int OFF_B1P = OFF_F3 + 4 * 64 * 2;  // biases (linear = pair-packed)
constexpr int OFF_B2P = OFF_B1P + 64;
constexpr int OFF_B3P = OFF_B2P + 64;         // 72
constexpr int OFF_FB1P = OFF_B3P + 72;
constexpr int OFF_FB2P = OFF_FB1P + 64;
constexpr int OFF_FB3P = OFF_FB2P + 64;       // 8
// scalar small weights
constexpr int OFF_UH1W = OFF_FB3P + 8;        // 8x13
constexpr int OFF_UH1B = OFF_UH1W + 104;      // 8
constexpr int OFF_G1W  = OFF_UH1B + 8;        // 8x8
constexpr int OFF_G1B  = OFF_G1W + 64;        // 8
constexpr int OFF_G2W  = OFF_G1B + 8;         // 8
constexpr int OFF_G2B  = OFF_G2W + 8;         // 1 (pad 4)
constexpr int OFF_UZ1  = OFF_G2B + 4;         // 8x4
constexpr int OFF_UZ2S = OFF_UZ1 + 32;        // 8x8
constexpr int OFF_UZ2Z = OFF_UZ2S + 64;       // 8
constexpr int OFF_DG1W = OFF_UZ2Z + 8;        // 8x8
constexpr int OFF_DG1B = OFF_DG1W + 64;       // 8
constexpr int OFF_DG2W = OFF_DG1B + 8;        // 8
constexpr int OFF_DG2B = OFF_DG2W + 8;        // 1 (pad 4)
constexpr int OFF_DZ2S = OFF_DG2B + 4;        // 8x8
constexpr int OFF_DZ2Z = OFF_DZ2S + 64;       // 8
// per-thread scratch: 24 rows x BLOCK (Zm0[0..7],Zm1[0..7],Zm2[0..7]; later Y0,Y1)
constexpr int OFF_ZM = OFF_DZ2Z + 8;          // = 19736
constexpr int SMEM_FLOATS = OFF_ZM + 24 * BLOCK;

// ---------------- f32x2 packed helpers ----------------
__device__ __forceinline__ ull pk2(float x) {
    ull r; unsigned xi = __float_as_uint(x);
    asm("mov.b64 %0, {%1, %1};" : "=l"(r) : "r"(xi));
    return r;
}
__device__ __forceinline__ ull f2fma(ull a, ull b, ull c) {
    ull d;
    asm("fma.rn.f32x2 %0, %1, %2, %3;" : "=l"(d) : "l"(a), "l"(b), "l"(c));
    return d;
}
__device__ __forceinline__ float2 up2(ull v) {
    unsigned lo, hi;
    asm("mov.b64 {%0, %1}, %2;" : "=r"(lo), "=r"(hi) : "l"(v));
    return make_float2(__uint_as_float(lo), __uint_as_float(hi));
}

__global__ void __launch_bounds__(BLOCK, 2) frame_gnn_kernel(
    const float* __restrict__ state,
    const float* __restrict__ up_Z1_w, const float* __restrict__ up_h1_w, const float* __restrict__ up_h1_b,
    const float* __restrict__ up_g1_w1, const float* __restrict__ up_g1_b1,
    const float* __restrict__ up_g1_w2, const float* __restrict__ up_g1_b2,
    const float* __restrict__ up_Z2_w,
    const float* __restrict__ up_m_w1, const float* __restrict__ up_m_b1,
    const float* __restrict__ up_m_w2, const float* __restrict__ up_m_b2,
    const float* __restrict__ up_m_w3, const float* __restrict__ up_m_b3,
    const float* __restrict__ dn_g1_w1, const float* __restrict__ dn_g1_b1,
    const float* __restrict__ dn_g1_w2, const float* __restrict__ dn_g1_b2,
    const float* __restrict__ dn_Z2_w,
    const float* __restrict__ fr_w1, const float* __restrict__ fr_b1,
    const float* __restrict__ fr_w2, const float* __restrict__ fr_b2,
    const float* __restrict__ fr_w3, const float* __restrict__ fr_b3,
    float* __restrict__ out)
{
    extern __shared__ float sm[];
    const int tid = threadIdx.x;

    // ---------------- stage + fold + pair-pack weights into shared ----------------
    if (tid < 64) {
        const int k = tid;
        const int base1 = OFF_L1 + (k >> 1) * 88 + (k & 1);   // (p*44)*2 + half
        const int basef = OFF_F1 + (k >> 1) * 88 + (k & 1);
        int p = 0;
        for (int a = 0; a < 8; a++) {
            for (int b = a; b < 8; b++) {
                float w = up_m_w1[k * 88 + a * 8 + b];
                float f = fr_w1[k * 80 + a * 8 + b];
                if (a != b) {
                    w += up_m_w1[k * 88 + b * 8 + a];
                    f += fr_w1[k * 80 + b * 8 + a];
                }
                sm[base1 + p * 2] = w;
                sm[basef + p * 2] = f;
                p++;
            }
        }
        for (int j = 0; j < 8; j++) {
            sm[base1 + (36 + j) * 2] = up_m_w1[k * 88 + 64 + j];
            sm[basef + (36 + j) * 2] = fr_w1[k * 80 + 64 + j];
        }
    }
    for (int e = tid; e < 64 * 64; e += BLOCK) {
        const int k = e >> 6, j = e & 63;
        const int d = ((k >> 1) * 64 + j) * 2 + (k & 1);
        sm[OFF_L2 + d] = up_m_w2[e];
        sm[OFF_F2 + d] = fr_w2[e];
    }
    for (int e = tid; e < 72 * 64; e += BLOCK) {
        const int k = e >> 6, j = e & 63;
        sm[OFF_L3 + ((k >> 1) * 64 + j) * 2 + (k & 1)] = up_m_w3[e];
    }
    for (int e = tid; e < 8 * 64; e += BLOCK) {
        const int k = e >> 6, j = e & 63;
        sm[OFF_F3 + ((k >> 1) * 64 + j) * 2 + (k & 1)] = fr_w3[e];
    }
    for (int i = tid; i < 64; i += BLOCK) {
        sm[OFF_B1P + i] = up_m_b1[i]; sm[OFF_B2P + i] = up_m_b2[i];
        sm[OFF_FB1P + i] = fr_b1[i];  sm[OFF_FB2P + i] = fr_b2[i];
    }
    for (int i = tid; i < 72; i += BLOCK) sm[OFF_B3P + i] = up_m_b3[i];
    for (int i = tid; i < 104; i += BLOCK) sm[OFF_UH1W + i] = up_h1_w[i];
    for (int i = tid; i < 32; i += BLOCK) sm[OFF_UZ1 + i] = up_Z1_w[i];
    for (int i = tid; i < 64; i += BLOCK) {
        const int k = i >> 3, j = i & 7;
        sm[OFF_G1W + i]  = up_g1_w1[k * 24 + j];
        sm[OFF_DG1W + i] = dn_g1_w1[k * 16 + j];
        sm[OFF_UZ2S + i] = up_Z2_w[k * 25 + j];
        sm[OFF_DZ2S + i] = dn_Z2_w[k * 17 + j];
    }
    if (tid < 8) {
        sm[OFF_FB3P + tid] = fr_b3[tid];
        sm[OFF_UH1B + tid] = up_h1_b[tid];
        sm[OFF_G1B + tid]  = up_g1_b1[tid];
        sm[OFF_G2W + tid]  = up_g1_w2[tid];
        sm[OFF_UZ2Z + tid] = up_Z2_w[tid * 25 + 24];
        sm[OFF_DG1B + tid] = dn_g1_b1[tid];
        sm[OFF_DG2W + tid] = dn_g1_w2[tid];
        sm[OFF_DZ2Z + tid] = dn_Z2_w[tid * 17 + 16];
    }
    if (tid == 0) { sm[OFF_G2B] = up_g1_b2[0]; sm[OFF_DG2B] = dn_g1_b2[0]; }
    __syncthreads();

    const ulonglong2* W1 = reinterpret_cast<const ulonglong2*>(sm + OFF_L1);
    const ulonglong2* W2 = reinterpret_cast<const ulonglong2*>(sm + OFF_L2);
    const ulonglong2* W3 = reinterpret_cast<const ulonglong2*>(sm + OFF_L3);
    const ulonglong2* G1 = reinterpret_cast<const ulonglong2*>(sm + OFF_F1);
    const ulonglong2* G2 = reinterpret_cast<const ulonglong2*>(sm + OFF_F2);
    const ulonglong2* G3 = reinterpret_cast<const ulonglong2*>(sm + OFF_F3);
    const ull* B1P = reinterpret_cast<const ull*>(sm + OFF_B1P);
    const ull* B2P = reinterpret_cast<const ull*>(sm + OFF_B2P);
    const ull* B3P = reinterpret_cast<const ull*>(sm + OFF_B3P);
    const ull* FB1P = reinterpret_cast<const ull*>(sm + OFF_FB1P);
    const ull* FB2P = reinterpret_cast<const ull*>(sm + OFF_FB2P);
    const ull* FB3P = reinterpret_cast<const ull*>(sm + OFF_FB3P);
    float* scr = sm + OFF_ZM + tid;   // per-thread scratch, row stride BLOCK

    // ---------------- per-row compute ----------------
    const int row = blockIdx.x * BLOCK + tid;
    const float* s = state + (size_t)row * 25;
    float* o = out + (size_t)row * 25;

    float h0[13];
#pragma unroll
    for (int i = 0; i < 4; i++) { float v = s[i]; h0[i] = v; o[i] = v; }
#pragma unroll
    for (int i = 0; i < 9; i++) { float v = s[16 + i]; h0[4 + i] = v; o[16 + i] = v; }

    // hm8 = relu(up_h1 @ h0 + b)
    float hm8[8];
#pragma unroll
    for (int k = 0; k < 8; k++) {
        float a = sm[OFF_UH1B + k];
#pragma unroll
        for (int i = 0; i < 13; i++) a += h0[i] * sm[OFF_UH1W + k * 13 + i];
        hm8[k] = fmaxf(a, 0.f);
    }
    // gs (scalar gate)
    float gs = sm[OFF_G2B];
#pragma unroll
    for (int k = 0; k < 8; k++) {
        float a = sm[OFF_G1B + k];
#pragma unroll
        for (int i = 0; i < 8; i++) a += hm8[i] * sm[OFF_G1W + k * 8 + i];
        gs += fmaxf(a, 0.f) * sm[OFF_G2W + k];
    }
    // Zm = [Z0 @ up_Z1^T, 0, (0,0,gs)] @ up_Z2^T
    float Zm0[8], Zm1[8], Zm2a[8];
    {
        float Z0x[4], Z0y[4], Z0z[4];
#pragma unroll
        for (int j = 0; j < 4; j++) { Z0x[j] = s[4 + 3 * j]; Z0y[j] = s[5 + 3 * j]; Z0z[j] = s[6 + 3 * j]; }
        float Zu0[8], Zu1[8], Zu2[8];
#pragma unroll
        for (int k = 0; k < 8; k++) {
            float a0 = 0.f, a1 = 0.f, a2 = 0.f;
#pragma unroll
            for (int j = 0; j < 4; j++) {
                float w = sm[OFF_UZ1 + k * 4 + j];
                a0 += Z0x[j] * w; a1 += Z0y[j] * w; a2 += Z0z[j] * w;
            }
            Zu0[k] = a0; Zu1[k] = a1; Zu2[k] = a2;
        }
#pragma unroll
        for (int k = 0; k < 8; k++) {
            float a0 = 0.f, a1 = 0.f, a2 = 0.f;
#pragma unroll
            for (int m = 0; m < 8; m++) {
                float w = sm[OFF_UZ2S + k * 8 + m];
                a0 += Zu0[m] * w; a1 += Zu1[m] * w; a2 += Zu2[m] * w;
            }
            a2 += gs * sm[OFF_UZ2Z + k];
            Zm0[k] = a0; Zm1[k] = a1; Zm2a[k] = a2;
        }
    }
    // Gram (36 unique) + Frobenius norm; xv[36..43]=hm8
    float xv[44];
    float nrm = 0.f;
    {
        int p = 0;
#pragma unroll
        for (int a = 0; a < 8; a++)
#pragma unroll
            for (int b = a; b < 8; b++) {
                float v = Zm0[a] * Zm0[b] + Zm1[a] * Zm1[b] + Zm2a[a] * Zm2a[b];
                xv[p] = v;
                nrm += (a == b) ? v * v : 2.f * v * v;
                p++;
            }
    }
#pragma unroll
    for (int j = 0; j < 8; j++) xv[36 + j] = hm8[j];
    const float invFn = 1.f / (sqrtf(nrm) + 1.f);

    // spill Zm to scratch (needed again only in layer3 consumption)
#pragma unroll
    for (int j = 0; j < 8; j++) {
        scr[j * BLOCK] = Zm0[j];
        scr[(8 + j) * BLOCK] = Zm1[j];
        scr[(16 + j) * BLOCK] = Zm2a[j];
    }

    // ---- up_m layer1: 64 out (32 pairs), K=44, relu ----
    float t1[64];
#pragma unroll
    for (int c = 0; c < 2; c++) {
        ull acc[16];
#pragma unroll
        for (int p = 0; p < 16; p++) acc[p] = B1P[c * 16 + p];
#pragma unroll
        for (int t = 0; t < 22; t++) {
            ull xa = pk2(xv[2 * t]), xb = pk2(xv[2 * t + 1]);
#pragma unroll
            for (int p = 0; p < 16; p++) {
                ulonglong2 wv = W1[(c * 16 + p) * 22 + t];
                acc[p] = f2fma(wv.x, xa, acc[p]);
                acc[p] = f2fma(wv.y, xb, acc[p]);
            }
        }
#pragma unroll
        for (int p = 0; p < 16; p++) {
            float2 r = up2(acc[p]);
            t1[c * 32 + 2 * p] = fmaxf(r.x, 0.f);
            t1[c * 32 + 2 * p + 1] = fmaxf(r.y, 0.f);
        }
    }
    // ---- up_m layer2: 64 out, K=64, relu ----
    float t2[64];
#pragma unroll
    for (int c = 0; c < 2; c++) {
        ull acc[16];
#pragma unroll
        for (int p = 0; p < 16; p++) acc[p] = B2P[c * 16 + p];
#pragma unroll
        for (int t = 0; t < 32; t++) {
            ull xa = pk2(t1[2 * t]), xb = pk2(t1[2 * t + 1]);
#pragma unroll
            for (int p = 0; p < 16; p++) {
                ulonglong2 wv = W2[(c * 16 + p) * 32 + t];
                acc[p] = f2fma(wv.x, xa, acc[p]);
                acc[p] = f2fma(wv.y, xb, acc[p]);
            }
        }
#pragma unroll
        for (int p = 0; p < 16; p++) {
            float2 r = up2(acc[p]);
            t2[c * 32 + 2 * p] = fmaxf(r.x, 0.f);
            t2[c * 32 + 2 * p + 1] = fmaxf(r.y, 0.f);
        }
    }
    // ---- up_m layer3: 72 out (36 pairs), K=64, fused consumption ----
    float uZ0[8], uZ1[8], uZ2[8], hm2[8];
#pragma unroll
    for (int k = 0; k < 8; k++) { uZ0[k] = 0.f; uZ1[k] = 0.f; uZ2[k] = 0.f; }
    {
        float zj0 = 0.f, zj1 = 0.f, zj2 = 0.f;
#pragma unroll
        for (int c = 0; c < 6; c++) {
            ull acc[6];
#pragma unroll
            for (int q = 0; q < 6; q++) acc[q] = B3P[c * 6 + q];
#pragma unroll
            for (int t = 0; t < 32; t++) {
                ull xa = pk2(t2[2 * t]), xb = pk2(t2[2 * t + 1]);
#pragma unroll
                for (int q = 0; q < 6; q++) {
                    ulonglong2 wv = W3[(c * 6 + q) * 32 + t];
                    acc[q] = f2fma(wv.x, xa, acc[q]);
                    acc[q] = f2fma(wv.y, xb, acc[q]);
                }
            }
#pragma unroll
            for (int q = 0; q < 6; q++) {
                float2 mm = up2(acc[q]);
                float mv0 = mm.x * invFn, mv1 = mm.y * invFn;
                const int i0 = (c * 6 + q) * 2;
#pragma unroll
                for (int h = 0; h < 2; h++) {
                    const float m = (h == 0) ? mv0 : mv1;
                    const int idx = i0 + h;
                    if (idx < 64) {
                        const int j = idx >> 3, k = idx & 7;
                        if (k == 0) {
                            zj0 = scr[j * BLOCK];
                            zj1 = scr[(8 + j) * BLOCK];
                            zj2 = scr[(16 + j) * BLOCK];
                        }
                        uZ0[k] += zj0 * m; uZ1[k] += zj1 * m; uZ2[k] += zj2 * m;
                    } else {
                        hm2[idx - 64] = fmaxf(m, 0.f);
                    }
                }
            }
        }
    }
    // gs2
    float gs2 = sm[OFF_DG2B];
#pragma unroll
    for (int k = 0; k < 8; k++) {
        float a = sm[OFF_DG1B + k];
#pragma unroll
        for (int i = 0; i < 8; i++) a += hm2[i] * sm[OFF_DG1W + k * 8 + i];
        gs2 += fmaxf(a, 0.f) * sm[OFF_DG2W + k];
    }
    // Y = [uZ, 0, (0,0,gs2)] @ dn_Z2^T
    float Y0[8], Y1[8], Y2[8];
#pragma unroll
    for (int k = 0; k < 8; k++) {
        float a0 = 0.f, a1 = 0.f, a2 = 0.f;
#pragma unroll
        for (int j = 0; j < 8; j++) {
            float w = sm[OFF_DZ2S + k * 8 + j];
            a0 += uZ0[j] * w; a1 += uZ1[j] * w; a2 += uZ2[j] * w;
        }
        a2 += gs2 * sm[OFF_DZ2Z + k];
        Y0[k] = a0; Y1[k] = a1; Y2[k] = a2;
    }
    // M2f pairs + norm; xv[36..43]=hm2
    float nrm2 = 0.f;
    {
        int p = 0;
#pragma unroll
        for (int a = 0; a < 8; a++)
#pragma unroll
            for (int b = a; b < 8; b++) {
                float v = Y0[a] * Y0[b] + Y1[a] * Y1[b] + Y2[a] * Y2[b];
                xv[p] = v;
                nrm2 += (a == b) ? v * v : 2.f * v * v;
                p++;
            }
    }
#pragma unroll
    for (int j = 0; j < 8; j++) xv[36 + j] = hm2[j];
    const float invFn2 = 1.f / (sqrtf(nrm2) + 1.f);

    // spill Y0,Y1 into scratch rows 0..15 (Zm is dead)
#pragma unroll
    for (int k = 0; k < 8; k++) {
        scr[k * BLOCK] = Y0[k];
        scr[(8 + k) * BLOCK] = Y1[k];
    }

    // ---- fr layer1: K=44, relu ----
    float f1[64];
#pragma unroll
    for (int c = 0; c < 2; c++) {
        ull acc[16];
#pragma unroll
        for (int p = 0; p < 16; p++) acc[p] = FB1P[c * 16 + p];
#pragma unroll
        for (int t = 0; t < 22; t++) {
            ull xa = pk2(xv[2 * t]), xb = pk2(xv[2 * t + 1]);
#pragma unroll
            for (int p = 0; p < 16; p++) {
                ulonglong2 wv = G1[(c * 16 + p) * 22 + t];
                acc[p] = f2fma(wv.x, xa, acc[p]);
                acc[p] = f2fma(wv.y, xb, acc[p]);
            }
        }
#pragma unroll
        for (int p = 0; p < 16; p++) {
            float2 r = up2(acc[p]);
            f1[c * 32 + 2 * p] = fmaxf(r.x, 0.f);
            f1[c * 32 + 2 * p + 1] = fmaxf(r.y, 0.f);
        }
    }
    // ---- fr layer2: K=64, relu ----
    float f2[64];
#pragma unroll
    for (int c = 0; c < 2; c++) {
        ull acc[16];
#pragma unroll
        for (int p = 0; p < 16; p++) acc[p] = FB2P[c * 16 + p];
#pragma unroll
        for (int t = 0; t < 32; t++) {
            ull xa = pk2(f1[2 * t]), xb = pk2(f1[2 * t + 1]);
#pragma unroll
            for (int p = 0; p < 16; p++) {
                ulonglong2 wv = G2[(c * 16 + p) * 32 + t];
                acc[p] = f2fma(wv.x, xa, acc[p]);
                acc[p] = f2fma(wv.y, xb, acc[p]);
            }
        }
#pragma unroll
        for (int p = 0; p < 16; p++) {
            float2 r = up2(acc[p]);
            f2[c * 32 + 2 * p] = fmaxf(r.x, 0.f);
            f2[c * 32 + 2 * p + 1] = fmaxf(r.y, 0.f);
        }
    }
    // ---- fr layer3: 8 out (4 pairs), K=64 ----
    float frv[8];
    {
        ull acc[4];
#pragma unroll
        for (int p = 0; p < 4; p++) acc[p] = FB3P[p];
#pragma unroll
        for (int t = 0; t < 32; t++) {
            ull xa = pk2(f2[2 * t]), xb = pk2(f2[2 * t + 1]);
#pragma unroll
            for (int p = 0; p < 4; p++) {
                ulonglong2 wv = G3[p * 32 + t];
                acc[p] = f2fma(wv.x, xa, acc[p]);
                acc[p] = f2fma(wv.y, xb, acc[p]);
            }
        }
#pragma unroll
        for (int p = 0; p < 4; p++) {
            float2 r = up2(acc[p]);
            frv[2 * p] = r.x * invFn2;
            frv[2 * p + 1] = r.y * invFn2;
        }
    }
    // frame x,y from stashed Y0,Y1
    float fx = 0.f, fy = 0.f;
#pragma unroll
    for (int k = 0; k < 8; k++) {
        fx += scr[k * BLOCK] * frv[k];
        fy += scr[(8 + k) * BLOCK] * frv[k];
    }
    const float n = sqrtf(fx * fx + fy * fy) + 1e-6f;
    const float u1x = fx / n, u1y = fy / n;

    // reload Z0 from global (L2-resident), rotate, write out[4:16]
#pragma unroll
    for (int j = 0; j < 4; j++) {
        const float zx = __ldg(&s[4 + 3 * j]);
        const float zy = __ldg(&s[5 + 3 * j]);
        const float zz = __ldg(&s[6 + 3 * j]);
        o[4 + 3 * j]     = u1x * zx + u1y * zy;
        o[4 + 3 * j + 1] = -u1y * zx + u1x * zy;
        o[4 + 3 * j + 2] = zz;
    }
}

extern "C" void kernel_launch(void* const* d_in, const int* in_sizes, int n_in,
                              void* d_out, int out_size) {
    (void)in_sizes; (void)n_in; (void)out_size;
    const size_t smem_bytes = SMEM_FLOATS * sizeof(float);
    cudaFuncSetAttribute(frame_gnn_kernel, cudaFuncAttributeMaxDynamicSharedMemorySize,
                         (int)smem_bytes);
    frame_gnn_kernel<<<NROWS / BLOCK, BLOCK, smem_bytes>>>(
        (const float*)d_in[0],
        (const float*)d_in[1], (const float*)d_in[2], (const float*)d_in[3],
        (const float*)d_in[4], (const float*)d_in[5], (const float*)d_in[6], (const float*)d_in[7],
        (const float*)d_in[8],
        (const float*)d_in[9], (const float*)d_in[10], (const float*)d_in[11], (const float*)d_in[12],
        (const float*)d_in[13], (const float*)d_in[14],
        (const float*)d_in[15], (const float*)d_in[16], (const float*)d_in[17], (const float*)d_in[18],
        (const float*)d_in[19],
        (const float*)d_in[20], (const float*)d_in[21], (const float*)d_in[22], (const float*)d_in[23],
        (const float*)d_in[24], (const float*)d_in[25],
        (float*)d_out);
}

// round 4
// speedup vs baseline: 1.7541x; 1.0434x over previous
#include <cuda_runtime.h>

#define BLOCK 256
#define NROWS 262144

using ull = unsigned long long;

// ---------------- shared memory layout (floats) ----------------
// Packed pair-interleaved weights: element (pair p, input j) at OFF + (p*K + j)*2,
// storing (W[2p][j], W[2p+1][j]) as consecutive floats (lo, hi of a b64).
constexpr int OFF_L1  = 0;                    // up_m_w1 folded: 32 pairs x 44
constexpr int OFF_L2  = OFF_L1 + 32 * 44 * 2; // up_m_w2: 32 pairs x 64
constexpr int OFF_L3  = OFF_L2 + 32 * 64 * 2; // up_m_w3: 36 pairs x 64
constexpr int OFF_F1  = OFF_L3 + 36 * 64 * 2; // fr_w1 folded: 32 x 44
constexpr int OFF_F2  = OFF_F1 + 32 * 44 * 2; // fr_w2: 32 x 64
constexpr int OFF_F3  = OFF_F2 + 32 * 64 * 2; // fr_w3: 4 x 64
constexpr int OFF_B1P = OFF_F3 + 4 * 64 * 2;  // biases (linear = pair-packed)
constexpr int OFF_B2P = OFF_B1P + 64;
constexpr int OFF_B3P = OFF_B2P + 64;         // 72
constexpr int OFF_FB1P = OFF_B3P + 72;
constexpr int OFF_FB2P = OFF_FB1P + 64;
constexpr int OFF_FB3P = OFF_FB2P + 64;       // 8
// scalar small weights
constexpr int OFF_UH1W = OFF_FB3P + 8;        // 8x13
constexpr int OFF_UH1B = OFF_UH1W + 104;      // 8
constexpr int OFF_G1W  = OFF_UH1B + 8;        // 8x8
constexpr int OFF_G1B  = OFF_G1W + 64;        // 8
constexpr int OFF_G2W  = OFF_G1B + 8;         // 8
constexpr int OFF_G2B  = OFF_G2W + 8;         // 1 (pad 4)
constexpr int OFF_UZ1  = OFF_G2B + 4;         // 8x4
constexpr int OFF_UZ2S = OFF_UZ1 + 32;        // 8x8
constexpr int OFF_UZ2Z = OFF_UZ2S + 64;       // 8
constexpr int OFF_DG1W = OFF_UZ2Z + 8;        // 8x8
constexpr int OFF_DG1B = OFF_DG1W + 64;       // 8
constexpr int OFF_DG2W = OFF_DG1B + 8;        // 8
constexpr int OFF_DG2B = OFF_DG2W + 8;        // 1 (pad 4)
constexpr int OFF_DZ2S = OFF_DG2B + 4;        // 8x8
constexpr int OFF_DZ2Z = OFF_DZ2S + 64;       // 8
// per-thread scratch: 24 rows x BLOCK (Zm0,Zm1,Zm2; later Y0,Y1)
constexpr int OFF_ZM = OFF_DZ2Z + 8;
constexpr int SMEM_FLOATS = OFF_ZM + 24 * BLOCK;

// ---------------- f32x2 packed helpers ----------------
__device__ __forceinline__ ull pk2(float x) {
    ull r; unsigned xi = __float_as_uint(x);
    asm("mov.b64 %0, {%1, %1};" : "=l"(r) : "r"(xi));
    return r;
}
__device__ __forceinline__ ull f2fma(ull a, ull b, ull c) {
    ull d;
    asm("fma.rn.f32x2 %0, %1, %2, %3;" : "=l"(d) : "l"(a), "l"(b), "l"(c));
    return d;
}
__device__ __forceinline__ float2 up2(ull v) {
    unsigned lo, hi;
    asm("mov.b64 {%0, %1}, %2;" : "=r"(lo), "=r"(hi) : "l"(v));
    return make_float2(__uint_as_float(lo), __uint_as_float(hi));
}

// One chunk of 4 output-pairs over KHALF b64-steps with double-buffered
// weight prefetch: next iteration's 4 LDS.128 issue a full iteration before
// their consumption, covering the 29-cycle LDS latency.
template<int KHALF>
__device__ __forceinline__ void chunk4(const ulonglong2* __restrict__ Wb,
                                       const float* __restrict__ x,
                                       ull acc[4])
{
    ulonglong2 cur[4], nxt[4];
#pragma unroll
    for (int p = 0; p < 4; p++) cur[p] = Wb[p * KHALF];
#pragma unroll
    for (int t = 0; t < KHALF; t++) {
#pragma unroll
        for (int p = 0; p < 4; p++)
            nxt[p] = (t + 1 < KHALF) ? Wb[p * KHALF + t + 1] : cur[p];
        ull xa = pk2(x[2 * t]), xb = pk2(x[2 * t + 1]);
#pragma unroll
        for (int p = 0; p < 4; p++) {
            acc[p] = f2fma(cur[p].x, xa, acc[p]);
            acc[p] = f2fma(cur[p].y, xb, acc[p]);
        }
#pragma unroll
        for (int p = 0; p < 4; p++) cur[p] = nxt[p];
    }
}

template<int KHALF, int NPAIRS, bool RELU>
__device__ __forceinline__ void mlp_layer(const ulonglong2* __restrict__ W,
                                          const ull* __restrict__ Bp,
                                          const float* __restrict__ x,
                                          float* __restrict__ y)
{
#pragma unroll
    for (int c = 0; c < NPAIRS / 4; c++) {
        ull acc[4];
#pragma unroll
        for (int p = 0; p < 4; p++) acc[p] = Bp[c * 4 + p];
        chunk4<KHALF>(W + (c * 4) * KHALF, x, acc);
#pragma unroll
        for (int p = 0; p < 4; p++) {
            float2 r = up2(acc[p]);
            if (RELU) { r.x = fmaxf(r.x, 0.f); r.y = fmaxf(r.y, 0.f); }
            y[c * 8 + 2 * p] = r.x;
            y[c * 8 + 2 * p + 1] = r.y;
        }
    }
}

__global__ void __launch_bounds__(BLOCK, 2) frame_gnn_kernel(
    const float* __restrict__ state,
    const float* __restrict__ up_Z1_w, const float* __restrict__ up_h1_w, const float* __restrict__ up_h1_b,
    const float* __restrict__ up_g1_w1, const float* __restrict__ up_g1_b1,
    const float* __restrict__ up_g1_w2, const float* __restrict__ up_g1_b2,
    const float* __restrict__ up_Z2_w,
    const float* __restrict__ up_m_w1, const float* __restrict__ up_m_b1,
    const float* __restrict__ up_m_w2, const float* __restrict__ up_m_b2,
    const float* __restrict__ up_m_w3, const float* __restrict__ up_m_b3,
    const float* __restrict__ dn_g1_w1, const float* __restrict__ dn_g1_b1,
    const float* __restrict__ dn_g1_w2, const float* __restrict__ dn_g1_b2,
    const float* __restrict__ dn_Z2_w,
    const float* __restrict__ fr_w1, const float* __restrict__ fr_b1,
    const float* __restrict__ fr_w2, const float* __restrict__ fr_b2,
    const float* __restrict__ fr_w3, const float* __restrict__ fr_b3,
    float* __restrict__ out)
{
    extern __shared__ float sm[];
    const int tid = threadIdx.x;

    // ---------------- stage + fold + pair-pack weights into shared ----------------
    if (tid < 64) {
        const int k = tid;
        const int base1 = OFF_L1 + (k >> 1) * 88 + (k & 1);
        const int basef = OFF_F1 + (k >> 1) * 88 + (k & 1);
        int p = 0;
        for (int a = 0; a < 8; a++) {
            for (int b = a; b < 8; b++) {
                float w = up_m_w1[k * 88 + a * 8 + b];
                float f = fr_w1[k * 80 + a * 8 + b];
                if (a != b) {
                    w += up_m_w1[k * 88 + b * 8 + a];
                    f += fr_w1[k * 80 + b * 8 + a];
                }
                sm[base1 + p * 2] = w;
                sm[basef + p * 2] = f;
                p++;
            }
        }
        for (int j = 0; j < 8; j++) {
            sm[base1 + (36 + j) * 2] = up_m_w1[k * 88 + 64 + j];
            sm[basef + (36 + j) * 2] = fr_w1[k * 80 + 64 + j];
        }
    }
    for (int e = tid; e < 64 * 64; e += BLOCK) {
        const int k = e >> 6, j = e & 63;
        const int d = ((k >> 1) * 64 + j) * 2 + (k & 1);
        sm[OFF_L2 + d] = up_m_w2[e];
        sm[OFF_F2 + d] = fr_w2[e];
    }
    for (int e = tid; e < 72 * 64; e += BLOCK) {
        const int k = e >> 6, j = e & 63;
        sm[OFF_L3 + ((k >> 1) * 64 + j) * 2 + (k & 1)] = up_m_w3[e];
    }
    for (int e = tid; e < 8 * 64; e += BLOCK) {
        const int k = e >> 6, j = e & 63;
        sm[OFF_F3 + ((k >> 1) * 64 + j) * 2 + (k & 1)] = fr_w3[e];
    }
    for (int i = tid; i < 64; i += BLOCK) {
        sm[OFF_B1P + i] = up_m_b1[i]; sm[OFF_B2P + i] = up_m_b2[i];
        sm[OFF_FB1P + i] = fr_b1[i];  sm[OFF_FB2P + i] = fr_b2[i];
    }
    for (int i = tid; i < 72; i += BLOCK) sm[OFF_B3P + i] = up_m_b3[i];
    for (int i = tid; i < 104; i += BLOCK) sm[OFF_UH1W + i] = up_h1_w[i];
    for (int i = tid; i < 32; i += BLOCK) sm[OFF_UZ1 + i] = up_Z1_w[i];
    for (int i = tid; i < 64; i += BLOCK) {
        const int k = i >> 3, j = i & 7;
        sm[OFF_G1W + i]  = up_g1_w1[k * 24 + j];
        sm[OFF_DG1W + i] = dn_g1_w1[k * 16 + j];
        sm[OFF_UZ2S + i] = up_Z2_w[k * 25 + j];
        sm[OFF_DZ2S + i] = dn_Z2_w[k * 17 + j];
    }
    if (tid < 8) {
        sm[OFF_FB3P + tid] = fr_b3[tid];
        sm[OFF_UH1B + tid] = up_h1_b[tid];
        sm[OFF_G1B + tid]  = up_g1_b1[tid];
        sm[OFF_G2W + tid]  = up_g1_w2[tid];
        sm[OFF_UZ2Z + tid] = up_Z2_w[tid * 25 + 24];
        sm[OFF_DG1B + tid] = dn_g1_b1[tid];
        sm[OFF_DG2W + tid] = dn_g1_w2[tid];
        sm[OFF_DZ2Z + tid] = dn_Z2_w[tid * 17 + 16];
    }
    if (tid == 0) { sm[OFF_G2B] = up_g1_b2[0]; sm[OFF_DG2B] = dn_g1_b2[0]; }
    __syncthreads();

    const ulonglong2* W1 = reinterpret_cast<const ulonglong2*>(sm + OFF_L1);
    const ulonglong2* W2 = reinterpret_cast<const ulonglong2*>(sm + OFF_L2);
    const ulonglong2* W3 = reinterpret_cast<const ulonglong2*>(sm + OFF_L3);
    const ulonglong2* G1 = reinterpret_cast<const ulonglong2*>(sm + OFF_F1);
    const ulonglong2* G2 = reinterpret_cast<const ulonglong2*>(sm + OFF_F2);
    const ulonglong2* G3 = reinterpret_cast<const ulonglong2*>(sm + OFF_F3);
    const ull* B1P = reinterpret_cast<const ull*>(sm + OFF_B1P);
    const ull* B2P = reinterpret_cast<const ull*>(sm + OFF_B2P);
    const ull* B3P = reinterpret_cast<const ull*>(sm + OFF_B3P);
    const ull* FB1P = reinterpret_cast<const ull*>(sm + OFF_FB1P);
    const ull* FB2P = reinterpret_cast<const ull*>(sm + OFF_FB2P);
    const ull* FB3P = reinterpret_cast<const ull*>(sm + OFF_FB3P);
    float* scr = sm + OFF_ZM + tid;   // per-thread scratch, row stride BLOCK

    // ---------------- per-row compute ----------------
    const int row = blockIdx.x * BLOCK + tid;
    const float* s = state + (size_t)row * 25;
    float* o = out + (size_t)row * 25;

    float h0[13];
#pragma unroll
    for (int i = 0; i < 4; i++) { float v = s[i]; h0[i] = v; o[i] = v; }
#pragma unroll
    for (int i = 0; i < 9; i++) { float v = s[16 + i]; h0[4 + i] = v; o[16 + i] = v; }

    // hm8 = relu(up_h1 @ h0 + b)
    float hm8[8];
#pragma unroll
    for (int k = 0; k < 8; k++) {
        float a = sm[OFF_UH1B + k];
#pragma unroll
        for (int i = 0; i < 13; i++) a += h0[i] * sm[OFF_UH1W + k * 13 + i];
        hm8[k] = fmaxf(a, 0.f);
    }
    // gs (scalar gate)
    float gs = sm[OFF_G2B];
#pragma unroll
    for (int k = 0; k < 8; k++) {
        float a = sm[OFF_G1B + k];
#pragma unroll
        for (int i = 0; i < 8; i++) a += hm8[i] * sm[OFF_G1W + k * 8 + i];
        gs += fmaxf(a, 0.f) * sm[OFF_G2W + k];
    }
    // Zm = [Z0 @ up_Z1^T, 0, (0,0,gs)] @ up_Z2^T
    float Zm0[8], Zm1[8], Zm2a[8];
    {
        float Z0x[4], Z0y[4], Z0z[4];
#pragma unroll
        for (int j = 0; j < 4; j++) { Z0x[j] = s[4 + 3 * j]; Z0y[j] = s[5 + 3 * j]; Z0z[j] = s[6 + 3 * j]; }
        float Zu0[8], Zu1[8], Zu2[8];
#pragma unroll
        for (int k = 0; k < 8; k++) {
            float a0 = 0.f, a1 = 0.f, a2 = 0.f;
#pragma unroll
            for (int j = 0; j < 4; j++) {
                float w = sm[OFF_UZ1 + k * 4 + j];
                a0 += Z0x[j] * w; a1 += Z0y[j] * w; a2 += Z0z[j] * w;
            }
            Zu0[k] = a0; Zu1[k] = a1; Zu2[k] = a2;
        }
#pragma unroll
        for (int k = 0; k < 8; k++) {
            float a0 = 0.f, a1 = 0.f, a2 = 0.f;
#pragma unroll
            for (int m = 0; m < 8; m++) {
                float w = sm[OFF_UZ2S + k * 8 + m];
                a0 += Zu0[m] * w; a1 += Zu1[m] * w; a2 += Zu2[m] * w;
            }
            a2 += gs * sm[OFF_UZ2Z + k];
            Zm0[k] = a0; Zm1[k] = a1; Zm2a[k] = a2;
        }
    }
    // Gram (36 unique) + Frobenius norm; xv[36..43]=hm8
    float xv[44];
    float nrm = 0.f;
    {
        int p = 0;
#pragma unroll
        for (int a = 0; a < 8; a++)
#pragma unroll
            for (int b = a; b < 8; b++) {
                float v = Zm0[a] * Zm0[b] + Zm1[a] * Zm1[b] + Zm2a[a] * Zm2a[b];
                xv[p] = v;
                nrm += (a == b) ? v * v : 2.f * v * v;
                p++;
            }
    }
#pragma unroll
    for (int j = 0; j < 8; j++) xv[36 + j] = hm8[j];
    const float invFn = 1.f / (sqrtf(nrm) + 1.f);

    // spill Zm to scratch (reused in layer3 consumption)
#pragma unroll
    for (int j = 0; j < 8; j++) {
        scr[j * BLOCK] = Zm0[j];
        scr[(8 + j) * BLOCK] = Zm1[j];
        scr[(16 + j) * BLOCK] = Zm2a[j];
    }

    // ---- up_m layer1 (K=44) + layer2 (K=64), relu ----
    float t1[64];
    mlp_layer<22, 32, true>(W1, B1P, xv, t1);
    float t2[64];
    mlp_layer<32, 32, true>(W2, B2P, t1, t2);

    // ---- up_m layer3: 72 out (9 chunks of 4 pairs = 8 outputs), fused consumption ----
    float uZ0[8], uZ1[8], uZ2[8], hm2[8];
#pragma unroll
    for (int k = 0; k < 8; k++) { uZ0[k] = 0.f; uZ1[k] = 0.f; uZ2[k] = 0.f; }
#pragma unroll
    for (int c = 0; c < 9; c++) {
        ull acc[4];
#pragma unroll
        for (int p = 0; p < 4; p++) acc[p] = B3P[c * 4 + p];
        chunk4<32>(W3 + (c * 4) * 32, t2, acc);
        if (c < 8) {
            // chunk c covers outputs 8c..8c+7 -> row j=c of M, all k
            const float zj0 = scr[c * BLOCK];
            const float zj1 = scr[(8 + c) * BLOCK];
            const float zj2 = scr[(16 + c) * BLOCK];
#pragma unroll
            for (int p = 0; p < 4; p++) {
                float2 mm = up2(acc[p]);
                const float m0 = mm.x * invFn, m1 = mm.y * invFn;
                const int k0 = 2 * p, k1 = 2 * p + 1;
                uZ0[k0] += zj0 * m0; uZ1[k0] += zj1 * m0; uZ2[k0] += zj2 * m0;
                uZ0[k1] += zj0 * m1; uZ1[k1] += zj1 * m1; uZ2[k1] += zj2 * m1;
            }
        } else {
#pragma unroll
            for (int p = 0; p < 4; p++) {
                float2 mm = up2(acc[p]);
                hm2[2 * p] = fmaxf(mm.x * invFn, 0.f);
                hm2[2 * p + 1] = fmaxf(mm.y * invFn, 0.f);
            }
        }
    }
    // gs2
    float gs2 = sm[OFF_DG2B];
#pragma unroll
    for (int k = 0; k < 8; k++) {
        float a = sm[OFF_DG1B + k];
#pragma unroll
        for (int i = 0; i < 8; i++) a += hm2[i] * sm[OFF_DG1W + k * 8 + i];
        gs2 += fmaxf(a, 0.f) * sm[OFF_DG2W + k];
    }
    // Y = [uZ, 0, (0,0,gs2)] @ dn_Z2^T
    float Y0[8], Y1[8], Y2[8];
#pragma unroll
    for (int k = 0; k < 8; k++) {
        float a0 = 0.f, a1 = 0.f, a2 = 0.f;
#pragma unroll
        for (int j = 0; j < 8; j++) {
            float w = sm[OFF_DZ2S + k * 8 + j];
            a0 += uZ0[j] * w; a1 += uZ1[j] * w; a2 += uZ2[j] * w;
        }
        a2 += gs2 * sm[OFF_DZ2Z + k];
        Y0[k] = a0; Y1[k] = a1; Y2[k] = a2;
    }
    // M2f pairs + norm; xv[36..43]=hm2
    float nrm2 = 0.f;
    {
        int p = 0;
#pragma unroll
        for (int a = 0; a < 8; a++)
#pragma unroll
            for (int b = a; b < 8; b++) {
                float v = Y0[a] * Y0[b] + Y1[a] * Y1[b] + Y2[a] * Y2[b];
                xv[p] = v;
                nrm2 += (a == b) ? v * v : 2.f * v * v;
                p++;
            }
    }
#pragma unroll
    for (int j = 0; j < 8; j++) xv[36 + j] = hm2[j];
    const float invFn2 = 1.f / (sqrtf(nrm2) + 1.f);

    // spill Y0,Y1 into scratch rows 0..15 (Zm is dead)
#pragma unroll
    for (int k = 0; k < 8; k++) {
        scr[k * BLOCK] = Y0[k];
        scr[(8 + k) * BLOCK] = Y1[k];
    }

    // ---- fr MLP ----
    float f1[64];
    mlp_layer<22, 32, true>(G1, FB1P, xv, f1);
    float f2[64];
    mlp_layer<32, 32, true>(G2, FB2P, f1, f2);
    float frv[8];
    {
        ull acc[4];
#pragma unroll
        for (int p = 0; p < 4; p++) acc[p] = FB3P[p];
        chunk4<32>(G3, f2, acc);
#pragma unroll
        for (int p = 0; p < 4; p++) {
            float2 r = up2(acc[p]);
            frv[2 * p] = r.x * invFn2;
            frv[2 * p + 1] = r.y * invFn2;
        }
    }
    // frame x,y from stashed Y0,Y1
    float fx = 0.f, fy = 0.f;
#pragma unroll
    for (int k = 0; k < 8; k++) {
        fx += scr[k * BLOCK] * frv[k];
        fy += scr[(8 + k) * BLOCK] * frv[k];
    }
    const float n = sqrtf(fx * fx + fy * fy) + 1e-6f;
    const float u1x = fx / n, u1y = fy / n;

    // reload Z0 from global (L2-resident), rotate, write out[4:16]
#pragma unroll
    for (int j = 0; j < 4; j++) {
        const float zx = __ldg(&s[4 + 3 * j]);
        const float zy = __ldg(&s[5 + 3 * j]);
        const float zz = __ldg(&s[6 + 3 * j]);
        o[4 + 3 * j]     = u1x * zx + u1y * zy;
        o[4 + 3 * j + 1] = -u1y * zx + u1x * zy;
        o[4 + 3 * j + 2] = zz;
    }
}

extern "C" void kernel_launch(void* const* d_in, const int* in_sizes, int n_in,
                              void* d_out, int out_size) {
    (void)in_sizes; (void)n_in; (void)out_size;
    const size_t smem_bytes = SMEM_FLOATS * sizeof(float);
    cudaFuncSetAttribute(frame_gnn_kernel, cudaFuncAttributeMaxDynamicSharedMemorySize,
                         (int)smem_bytes);
    frame_gnn_kernel<<<NROWS / BLOCK, BLOCK, smem_bytes>>>(
        (const float*)d_in[0],
        (const float*)d_in[1], (const float*)d_in[2], (const float*)d_in[3],
        (const float*)d_in[4], (const float*)d_in[5], (const float*)d_in[6], (const float*)d_in[7],
        (const float*)d_in[8],
        (const float*)d_in[9], (const float*)d_in[10], (const float*)d_in[11], (const float*)d_in[12],
        (const float*)d_in[13], (const float*)d_in[14],
        (const float*)d_in[15], (const float*)d_in[16], (const float*)d_in[17], (const float*)d_in[18],
        (const float*)d_in[19],
        (const float*)d_in[20], (const float*)d_in[21], (const float*)d_in[22], (const float*)d_in[23],
        (const float*)d_in[24], (const float*)d_in[25],
        (float*)d_out);
}